// round 8
// baseline (speedup 1.0000x reference)
#include <cuda_runtime.h>
#include <cuda_bf16.h>
#include <cstdint>

#define KC    512
#define DD    64
#define NN    2048
#define BB    64
#define TM    128
#define NTILES 1024          // (BB*NN)/TM
#define NTHREADS 512
#define GRID  148
#define L2E   1.4426950408889634f

// ---------------- smem layout (dynamic) ----------------
// A buffers are dual-use: raw fp32 tile (32KB) OR converted AH(16KB)+AL(16KB)
#define SMEM_A0   0          // 32KB
#define SMEM_A1   32768      // 32KB
#define SMEM_BH   65536      // 512 x 128B bf16 hi (64KB)
#define SMEM_BL   131072     // 64KB  (BL - BH = 65536)
#define SMEM_CW   196608     // float2[512] 4KB
#define SMEM_F2S0 200704     // float[128]
#define SMEM_F2S1 201216     // float[128]
#define SMEM_RED  201728     // float[16] + int flag
#define SMEM_TOTAL 201856

__device__ float g_part[NTILES];
__device__ int   g_count;    // zero-init; self-resets each launch

// ---------------- helpers ----------------
__device__ __forceinline__ uint32_t smem_u32(const void* p) {
    uint32_t a;
    asm("{ .reg .u64 t; cvta.to.shared.u64 t, %1; cvt.u32.u64 %0, t; }" : "=r"(a) : "l"(p));
    return a;
}
__device__ __forceinline__ float ex2f(float x) {
    float r; asm("ex2.approx.ftz.f32 %0, %1;" : "=f"(r) : "f"(x)); return r;
}
#define SWZ128(off) ((off) ^ (((off) >> 3) & 0x70))

__device__ __forceinline__ void cp_async16(uint32_t saddr, const void* gaddr) {
    asm volatile("cp.async.ca.shared.global [%0], [%1], 16;" :: "r"(saddr), "l"(gaddr));
}
#define CP_COMMIT() asm volatile("cp.async.commit_group;" ::: "memory")
#define CP_WAIT0()  asm volatile("cp.async.wait_group 0;" ::: "memory")

__device__ __forceinline__ void ldsm4(uint32_t addr, uint32_t* r) {
    asm volatile("ldmatrix.sync.aligned.m8n8.x4.shared.b16 {%0,%1,%2,%3}, [%4];"
        : "=r"(r[0]), "=r"(r[1]), "=r"(r[2]), "=r"(r[3]) : "r"(addr));
}
__device__ __forceinline__ void mma_bf16(float* c, const uint32_t* a, const uint32_t* b) {
    asm volatile(
        "mma.sync.aligned.m16n8k16.row.col.f32.bf16.bf16.f32 "
        "{%0,%1,%2,%3}, {%4,%5,%6,%7}, {%8,%9}, {%0,%1,%2,%3};"
        : "+f"(c[0]), "+f"(c[1]), "+f"(c[2]), "+f"(c[3])
        : "r"(a[0]), "r"(a[1]), "r"(a[2]), "r"(a[3]), "r"(b[0]), "r"(b[1]));
}

// split 8 floats -> (hi bf16, lo bf16) packed pairwise; ss += sum of squares
__device__ __forceinline__ void split8(const float* v, uint4& hi, uint4& lo, float& ss) {
    float r[8]; __nv_bfloat16 h[8];
#pragma unroll
    for (int i = 0; i < 8; i++) {
        float a = v[i];
        ss = fmaf(a, a, ss);
        h[i] = __float2bfloat16(a);
        r[i] = a - __bfloat162float(h[i]);
    }
    uint32_t* hp = (uint32_t*)&hi;
    uint32_t* lp = (uint32_t*)&lo;
#pragma unroll
    for (int i = 0; i < 4; i++) {
        __nv_bfloat162 th = __nv_bfloat162(h[2*i], h[2*i+1]);
        __nv_bfloat162 tl = __floats2bfloat162_rn(r[2*i], r[2*i+1]);
        hp[i] = *(uint32_t*)&th;
        lp[i] = *(uint32_t*)&tl;
    }
}

// In-place convert: raw fp32 tile in abuf[0..32768) -> AH[0..16384)+AL[16384..32768).
// Phase 1 (before barrier): read 16 floats to regs. Phase 2 (after): split+STS+f2.
__device__ __forceinline__ void conv_read(char* abuf, int tid, float* v16) {
    const float4* src = (const float4*)(abuf + (tid >> 2) * 256 + (tid & 3) * 64);
#pragma unroll
    for (int i = 0; i < 4; i++) *(float4*)&v16[i * 4] = src[i];
}
__device__ __forceinline__ void conv_write(char* abuf, int tid, int lane,
                                           const float* v16, float* f2s, float l2nb) {
    const int r = tid >> 2, q = tid & 3;
    float ss = 0.f;
#pragma unroll
    for (int j = 0; j < 2; j++) {
        uint4 hi, lo;
        split8(v16 + j * 8, hi, lo, ss);
        uint32_t sw = SWZ128((uint32_t)(r * 128 + (q * 2 + j) * 16));
        *(uint4*)(abuf + sw) = hi;
        *(uint4*)(abuf + 16384 + sw) = lo;
    }
    ss += __shfl_xor_sync(0xFFFFFFFFu, ss, 1);
    ss += __shfl_xor_sync(0xFFFFFFFFu, ss, 2);
    if ((lane & 3) == 0) f2s[r] = l2nb * ss;
}

// 16-col chunk MMA with cached A-hi fragments; term-major inner ordering.
__device__ __forceinline__ void mma_chunk16(
    float acc[2][2][4], const uint32_t ahc[2][4][4],
    uint32_t abase, uint32_t alx, uint32_t blx, uint32_t bcol_base) {
#pragma unroll
    for (int mt = 0; mt < 2; mt++)
#pragma unroll
        for (int h = 0; h < 2; h++)
#pragma unroll
            for (int q = 0; q < 4; q++) acc[mt][h][q] = 0.f;

#pragma unroll
    for (int kt = 0; kt < 4; kt++) {
        const uint32_t ka = ((uint32_t)(kt * 32)) ^ alx;
        const uint32_t kb = ((uint32_t)(kt * 32)) ^ blx;
        uint32_t al[2][4], bh[4], bl[4];
        ldsm4(abase + ka + 16384,        al[0]);
        ldsm4(abase + 2048 + ka + 16384, al[1]);
        ldsm4(bcol_base + kb,         bh);
        ldsm4(bcol_base + kb + 65536, bl);
        // term hh
#pragma unroll
        for (int mt = 0; mt < 2; mt++)
#pragma unroll
            for (int h = 0; h < 2; h++)
                mma_bf16(acc[mt][h], ahc[mt][kt], &bh[h * 2]);
        // term hl
#pragma unroll
        for (int mt = 0; mt < 2; mt++)
#pragma unroll
            for (int h = 0; h < 2; h++)
                mma_bf16(acc[mt][h], ahc[mt][kt], &bl[h * 2]);
        // term lh
#pragma unroll
        for (int mt = 0; mt < 2; mt++)
#pragma unroll
            for (int h = 0; h < 2; h++)
                mma_bf16(acc[mt][h], al[mt], &bh[h * 2]);
    }
}

__device__ __forceinline__ void epi_chunk16(
    const float acc[2][2][4], const float* __restrict__ f2s,
    const float2* __restrict__ cw, int cb, int rb, int lane,
    float coef, float& score) {
    const int ccol = cb + 2 * (lane & 3);
#pragma unroll
    for (int mt = 0; mt < 2; mt++) {
        const int r0 = rb + mt * 16 + (lane >> 2);
        const float f20 = f2s[r0], f21 = f2s[r0 + 8];
#pragma unroll
        for (int h = 0; h < 2; h++) {
            const float4 cwv = *(const float4*)(cw + ccol + h * 8);
            const float* a = acc[mt][h];
            float g0 = fminf(fmaf(coef, a[0], f20 + cwv.x), 0.f);
            float g1 = fminf(fmaf(coef, a[1], f20 + cwv.z), 0.f);
            float g2 = fminf(fmaf(coef, a[2], f21 + cwv.x), 0.f);
            float g3 = fminf(fmaf(coef, a[3], f21 + cwv.z), 0.f);
            score = fmaf(cwv.y, ex2f(g0), score);
            score = fmaf(cwv.w, ex2f(g1), score);
            score = fmaf(cwv.y, ex2f(g2), score);
            score = fmaf(cwv.w, ex2f(g3), score);
        }
    }
}

// ---------------------------------------------------------------------------
__global__ void __launch_bounds__(NTHREADS, 1)
main_kernel(const float* __restrict__ F,
            const float* __restrict__ C,
            const float* __restrict__ psi,
            const float* __restrict__ betap,
            float* __restrict__ out) {
    extern __shared__ __align__(1024) char smem[];
    const uint32_t sb = smem_u32(smem);
    const int tid  = threadIdx.x;
    const int lane = tid & 31;
    const int wid  = tid >> 5;          // 0..15

    float*  red = (float*)(smem + SMEM_RED);
    int*    flg = (int*)(smem + SMEM_RED + 64);
    float2* cw  = (float2*)(smem + SMEM_CW);

    const float beta = *betap;
    const float l2nb = -beta * L2E;          // < 0
    const float coef = -2.0f * l2nb;         // > 0

    // ---- softmax(psi): scratch in A1 region ----
    {
        float* rtmp = (float*)(smem + SMEM_A1);        // 512 floats
        float* ews  = rtmp + 512;                       // 512 floats
        float p = psi[tid];
        rtmp[tid] = p;
        __syncthreads();
#pragma unroll
        for (int s = 256; s > 0; s >>= 1) {
            if (tid < s) rtmp[tid] = fmaxf(rtmp[tid], rtmp[tid + s]);
            __syncthreads();
        }
        float mx = rtmp[0];
        __syncthreads();
        float e = ex2f((p - mx) * L2E);
        ews[tid] = e;
        rtmp[tid] = e;
        __syncthreads();
#pragma unroll
        for (int s = 256; s > 0; s >>= 1) {
            if (tid < s) rtmp[tid] += rtmp[tid + s];
            __syncthreads();
        }
        float rden = 1.0f / rtmp[0];
        __syncthreads();

        // ---- convert centers -> Bh/Bl (SW128), c2 partials in A0 region ----
        float* c2p = (float*)(smem + SMEM_A0);    // 4096 floats scratch
#pragma unroll
        for (int k = 0; k < 8; k++) {
            int i = tid + k * NTHREADS;
            int r = i >> 3, ck = i & 7;
            float v[8];
            const float4* src = (const float4*)(C + (size_t)r * DD + ck * 8);
            *(float4*)&v[0] = src[0];
            *(float4*)&v[4] = src[1];
            uint4 hi, lo; float ss = 0.f;
            split8(v, hi, lo, ss);
            c2p[i] = ss;
            uint32_t sw = SWZ128((uint32_t)(r * 128 + ck * 16));
            *(uint4*)(smem + SMEM_BH + sw) = hi;
            *(uint4*)(smem + SMEM_BL + sw) = lo;
        }
        __syncthreads();
        {
            float s = 0.f;
#pragma unroll
            for (int k = 0; k < 8; k++) s += c2p[tid * 8 + k];
            cw[tid] = make_float2(l2nb * s, ews[tid] * rden);
        }
        __syncthreads();   // scratch regions free
    }

    // ---- per-warp ldmatrix lane addressing ----
    const int rb    = (wid & 3) * 32;        // 32-row block
    const int cb0   = (wid >> 2) * 128;      // 128-col quadrant, 8 chunks of 16
    const int ncrot = ((wid >> 2) & 3) * 2;  // time-staggered chunk phase
    const int arow  = lane & 15;
    const uint32_t alx = (uint32_t)(((lane >> 4) * 16) ^ ((arow & 7) * 16));
    const uint32_t arowoff = (uint32_t)(rb + arow) * 128;
    const int bg = lane >> 3, br = lane & 7;
    const uint32_t blx = (uint32_t)(((bg & 1) * 16) ^ (br * 16));
    const int bnoff = br + (bg >> 1) * 8;

    // ---- prologue: stage + convert first tile into A0 ----
    {
        const char* gsrc = (const char*)(F + (size_t)blockIdx.x * TM * DD);
#pragma unroll
        for (int k = 0; k < 4; k++) {
            uint32_t off = (uint32_t)(tid * 16 + k * NTHREADS * 16);
            cp_async16(sb + SMEM_A0 + off, gsrc + off);
        }
        CP_COMMIT();
        CP_WAIT0();
        __syncthreads();
        float v16[16];
        conv_read(smem + SMEM_A0, tid, v16);
        __syncthreads();
        conv_write(smem + SMEM_A0, tid, lane, v16, (float*)(smem + SMEM_F2S0), l2nb);
    }

    int pcur = 0;

    // ================= tile loop (persistent) =================
#pragma unroll 1
    for (int t = blockIdx.x; t < NTILES; t += GRID, pcur ^= 1) {
        __syncthreads();   // B1: converted A(cur) + f2s(cur) visible

        const uint32_t acur = (pcur ? SMEM_A1 : SMEM_A0);
        const uint32_t anxt = (pcur ? SMEM_A0 : SMEM_A1);
        float* f2sc = (float*)(smem + (pcur ? SMEM_F2S1 : SMEM_F2S0));
        float* f2sn = (float*)(smem + (pcur ? SMEM_F2S0 : SMEM_F2S1));
        const uint32_t abase = sb + acur + arowoff;
        const bool havenext = (t + GRID < NTILES);

        // stage next tile (async, zero registers)
        if (havenext) {
            const char* gsrc = (const char*)(F + (size_t)(t + GRID) * TM * DD);
#pragma unroll
            for (int k = 0; k < 4; k++) {
                uint32_t off = (uint32_t)(tid * 16 + k * NTHREADS * 16);
                cp_async16(sb + anxt + off, gsrc + off);
            }
            CP_COMMIT();
        }

        // cache A-hi fragments for all 4 k-steps (32 regs)
        uint32_t ahc[2][4][4];
#pragma unroll
        for (int kt = 0; kt < 4; kt++) {
            const uint32_t ka = ((uint32_t)(kt * 32)) ^ alx;
            ldsm4(abase + ka,        ahc[0][kt]);
            ldsm4(abase + 2048 + ka, ahc[1][kt]);
        }

        float score = 0.f;
        float accA[2][2][4], accB[2][2][4];

        // software-pipelined 8 chunks: MMA(c+1) issues before epi(c)
        {
            const int cb = cb0 + (ncrot & 7) * 16;
            mma_chunk16(accA, ahc, abase, alx, blx,
                        sb + SMEM_BH + (uint32_t)(cb + bnoff) * 128);
        }
#pragma unroll
        for (int c = 1; c < 8; c++) {
            const int cb  = cb0 + ((c + ncrot) & 7) * 16;
            const int cbp = cb0 + ((c - 1 + ncrot) & 7) * 16;
            if (c & 1) {
                mma_chunk16(accB, ahc, abase, alx, blx,
                            sb + SMEM_BH + (uint32_t)(cb + bnoff) * 128);
                epi_chunk16(accA, f2sc, cw, cbp, rb, lane, coef, score);
            } else {
                mma_chunk16(accA, ahc, abase, alx, blx,
                            sb + SMEM_BH + (uint32_t)(cb + bnoff) * 128);
                epi_chunk16(accB, f2sc, cw, cbp, rb, lane, coef, score);
            }
        }
        epi_chunk16(accB, f2sc, cw, cb0 + ((7 + ncrot) & 7) * 16, rb, lane, coef, score);

        // ---- warp reduction ----
#pragma unroll
        for (int o = 16; o > 0; o >>= 1)
            score += __shfl_xor_sync(0xFFFFFFFFu, score, o);
        if (lane == 0) red[wid] = score;

        // ---- read raw next tile (pre-barrier phase of in-place convert) ----
        float v16[16];
        if (havenext) {
            CP_WAIT0();
            conv_read(smem + anxt, tid, v16);
        }
        __syncthreads();   // B3: red ready; raw reads done; MMA reads of cur done
        if (tid == 0) {
            float s = 0.f;
#pragma unroll
            for (int w = 0; w < 16; w++) s += red[w];
            g_part[t] = s;
        }
        if (havenext)
            conv_write(smem + anxt, tid, lane, v16, f2sn, l2nb);
    }

    // ---- last CTA folds partials into out ----
    __threadfence();
    if (tid == 0) {
        int p = atomicAdd(&g_count, 1);
        *flg = (p == GRID - 1);
    }
    __syncthreads();
    if (*flg) {
        __threadfence();
        if (tid < BB) {
            float s = 0.f;
#pragma unroll
            for (int i = 0; i < NTILES / BB; i++) s += g_part[tid * (NTILES / BB) + i];
            out[tid] = s * (1.0f / NN);
        }
        if (tid == 0) g_count = 0;   // reset for next graph replay
    }
}

// ---------------------------------------------------------------------------
extern "C" void kernel_launch(void* const* d_in, const int* in_sizes, int n_in,
                              void* d_out, int out_size) {
    const float* F       = (const float*)d_in[0];
    const float* centers = (const float*)d_in[1];
    const float* psi     = (const float*)d_in[2];
    const float* beta    = (const float*)d_in[3];
    float* out           = (float*)d_out;

    cudaFuncSetAttribute(main_kernel, cudaFuncAttributeMaxDynamicSharedMemorySize, SMEM_TOTAL);
    main_kernel<<<GRID, NTHREADS, SMEM_TOTAL>>>(F, centers, psi, beta, out);
}

// round 9
// speedup vs baseline: 1.4335x; 1.4335x over previous
#include <cuda_runtime.h>
#include <cuda_bf16.h>
#include <cstdint>

#define KC    512
#define DD    64
#define NN    2048
#define BB    64
#define TM    128
#define NTILES 1024          // (BB*NN)/TM
#define NTHREADS 256
#define GRID  148
#define L2E   1.4426950408889634f

// ---------------- smem layout (dynamic) ----------------
#define SMEM_A0   0          // 16KB (A hi, buf 0)
#define SMEM_A1   16384      // 16KB (A hi, buf 1)
#define SMEM_BH   32768      // 512 x 128B bf16 hi (64KB)
#define SMEM_BL   98304      // 64KB  (BL - BH = 65536)
#define SMEM_CW   163840     // float2[512] 4KB
#define SMEM_F2P0 167936     // float[1024] 4KB
#define SMEM_F2P1 172032     // 4KB
#define SMEM_F2S0 176128     // float[128]
#define SMEM_F2S1 176640     // float[128]
#define SMEM_RED  177152     // float[8] + int flag
#define SMEM_TOTAL 177216

__device__ float g_part[NTILES];
__device__ int   g_count;    // zero-init; self-resets each launch

// ---------------- helpers ----------------
__device__ __forceinline__ uint32_t smem_u32(const void* p) {
    uint32_t a;
    asm("{ .reg .u64 t; cvta.to.shared.u64 t, %1; cvt.u32.u64 %0, t; }" : "=r"(a) : "l"(p));
    return a;
}
__device__ __forceinline__ float ex2f(float x) {
    float r; asm("ex2.approx.ftz.f32 %0, %1;" : "=f"(r) : "f"(x)); return r;
}
#define SWZ128(off) ((off) ^ (((off) >> 3) & 0x70))

__device__ __forceinline__ void ldsm4(uint32_t addr, uint32_t* r) {
    asm volatile("ldmatrix.sync.aligned.m8n8.x4.shared.b16 {%0,%1,%2,%3}, [%4];"
        : "=r"(r[0]), "=r"(r[1]), "=r"(r[2]), "=r"(r[3]) : "r"(addr));
}
__device__ __forceinline__ void mma_bf16(float* c, const uint32_t* a, const uint32_t* b) {
    asm volatile(
        "mma.sync.aligned.m16n8k16.row.col.f32.bf16.bf16.f32 "
        "{%0,%1,%2,%3}, {%4,%5,%6,%7}, {%8,%9}, {%0,%1,%2,%3};"
        : "+f"(c[0]), "+f"(c[1]), "+f"(c[2]), "+f"(c[3])
        : "r"(a[0]), "r"(a[1]), "r"(a[2]), "r"(a[3]), "r"(b[0]), "r"(b[1]));
}

// split 8 floats -> (hi bf16, lo bf16) packed pairwise; ss += sum of squares
__device__ __forceinline__ void split8(const float* v, uint4& hi, uint4& lo, float& ss) {
    float r[8]; __nv_bfloat16 h[8];
#pragma unroll
    for (int i = 0; i < 8; i++) {
        float a = v[i];
        ss = fmaf(a, a, ss);
        h[i] = __float2bfloat16(a);
        r[i] = a - __bfloat162float(h[i]);
    }
    uint32_t* hp = (uint32_t*)&hi;
    uint32_t* lp = (uint32_t*)&lo;
#pragma unroll
    for (int i = 0; i < 4; i++) {
        __nv_bfloat162 th = __nv_bfloat162(h[2*i], h[2*i+1]);
        __nv_bfloat162 tl = __floats2bfloat162_rn(r[2*i], r[2*i+1]);
        hp[i] = *(uint32_t*)&th;
        lp[i] = *(uint32_t*)&tl;
    }
}

// round 8 floats -> hi bf16 packed pairwise; ss += sum of squares (fp32 exact)
__device__ __forceinline__ void round8(const float* v, uint4& hi, float& ss) {
    __nv_bfloat16 h[8];
#pragma unroll
    for (int i = 0; i < 8; i++) {
        float a = v[i];
        ss = fmaf(a, a, ss);
        h[i] = __float2bfloat16(a);
    }
    uint32_t* hp = (uint32_t*)&hi;
#pragma unroll
    for (int i = 0; i < 4; i++) {
        __nv_bfloat162 th = __nv_bfloat162(h[2*i], h[2*i+1]);
        hp[i] = *(uint32_t*)&th;
    }
}

// 32-col chunk MMA, 2-term (A-hi cached x B-hi + A-hi x B-lo), term-major.
__device__ __forceinline__ void mma_chunk32(
    float acc[2][4][4], const uint32_t ahc[2][4][4],
    uint32_t blx, uint32_t bcol_base) {
#pragma unroll
    for (int mt = 0; mt < 2; mt++)
#pragma unroll
        for (int nt = 0; nt < 4; nt++)
#pragma unroll
            for (int q = 0; q < 4; q++) acc[mt][nt][q] = 0.f;

#pragma unroll
    for (int kt = 0; kt < 4; kt++) {
        const uint32_t kb = ((uint32_t)(kt * 32)) ^ blx;
        uint32_t bh[2][4], bl[2][4];
#pragma unroll
        for (int np = 0; np < 2; np++) {
            const uint32_t bb = bcol_base + (uint32_t)(np * 16) * 128 + kb;
            ldsm4(bb,         bh[np]);
            ldsm4(bb + 65536, bl[np]);
        }
        // term: ah * bh   (8 independent HMMAs)
#pragma unroll
        for (int mt = 0; mt < 2; mt++)
#pragma unroll
            for (int np = 0; np < 2; np++)
#pragma unroll
                for (int h = 0; h < 2; h++)
                    mma_bf16(acc[mt][np*2+h], ahc[mt][kt], &bh[np][h*2]);
        // term: ah * bl
#pragma unroll
        for (int mt = 0; mt < 2; mt++)
#pragma unroll
            for (int np = 0; np < 2; np++)
#pragma unroll
                for (int h = 0; h < 2; h++)
                    mma_bf16(acc[mt][np*2+h], ahc[mt][kt], &bl[np][h*2]);
    }
}

__device__ __forceinline__ void epi_chunk32(
    const float acc[2][4][4], const float* __restrict__ f2s,
    const float2* __restrict__ cw, int cb, int rb, int lane,
    float coef, float& score) {
    const int ccol = cb + 2 * (lane & 3);
#pragma unroll
    for (int mt = 0; mt < 2; mt++) {
        const int r0 = rb + mt * 16 + (lane >> 2);
        const float f20 = f2s[r0], f21 = f2s[r0 + 8];
#pragma unroll
        for (int nt = 0; nt < 4; nt++) {
            const float4 cwv = *(const float4*)(cw + ccol + nt * 8);
            const float* a = acc[mt][nt];
            float g0 = fminf(fmaf(coef, a[0], f20 + cwv.x), 0.f);
            float g1 = fminf(fmaf(coef, a[1], f20 + cwv.z), 0.f);
            float g2 = fminf(fmaf(coef, a[2], f21 + cwv.x), 0.f);
            float g3 = fminf(fmaf(coef, a[3], f21 + cwv.z), 0.f);
            score = fmaf(cwv.y, ex2f(g0), score);
            score = fmaf(cwv.w, ex2f(g1), score);
            score = fmaf(cwv.y, ex2f(g2), score);
            score = fmaf(cwv.w, ex2f(g3), score);
        }
    }
}

// ---------------------------------------------------------------------------
__global__ void __launch_bounds__(NTHREADS, 1)
main_kernel(const float* __restrict__ F,
            const float* __restrict__ C,
            const float* __restrict__ psi,
            const float* __restrict__ betap,
            float* __restrict__ out) {
    extern __shared__ __align__(1024) char smem[];
    const uint32_t sb = smem_u32(smem);
    const int tid  = threadIdx.x;
    const int lane = tid & 31;
    const int wid  = tid >> 5;

    float*  red = (float*)(smem + SMEM_RED);
    int*    flg = (int*)(smem + SMEM_RED + 32);
    float2* cw  = (float2*)(smem + SMEM_CW);

    const float beta = *betap;
    const float l2nb = -beta * L2E;          // < 0
    const float coef = -2.0f * l2nb;         // > 0

    // ---- softmax(psi) (f2p0 region as scratch) ----
    {
        float* rtmp = (float*)(smem + SMEM_F2P0);
        float* ews  = rtmp + 256;            // [256..767]
        float p0 = psi[tid], p1 = psi[tid + 256];
        rtmp[tid] = fmaxf(p0, p1);
        __syncthreads();
#pragma unroll
        for (int s = 128; s > 0; s >>= 1) {
            if (tid < s) rtmp[tid] = fmaxf(rtmp[tid], rtmp[tid + s]);
            __syncthreads();
        }
        float mx = rtmp[0];
        __syncthreads();
        float e0 = ex2f((p0 - mx) * L2E), e1 = ex2f((p1 - mx) * L2E);
        ews[tid] = e0; ews[tid + 256] = e1;
        rtmp[tid] = e0 + e1;
        __syncthreads();
#pragma unroll
        for (int s = 128; s > 0; s >>= 1) {
            if (tid < s) rtmp[tid] += rtmp[tid + s];
            __syncthreads();
        }
        float rden = 1.0f / rtmp[0];
        __syncthreads();

        // ---- convert centers -> Bh/Bl (SW128), c2 partials in A region ----
        float* c2p = (float*)(smem + SMEM_A0);    // 4096 floats scratch (A0+A1)
        for (int i = tid; i < KC * 8; i += NTHREADS) {
            int r = i >> 3, ck = i & 7;
            float v[8];
            const float4* src = (const float4*)(C + (size_t)r * DD + ck * 8);
            *(float4*)&v[0] = src[0];
            *(float4*)&v[4] = src[1];
            uint4 hi, lo; float ss = 0.f;
            split8(v, hi, lo, ss);
            c2p[i] = ss;
            uint32_t sw = SWZ128((uint32_t)(r * 128 + ck * 16));
            *(uint4*)(smem + SMEM_BH + sw) = hi;
            *(uint4*)(smem + SMEM_BL + sw) = lo;
        }
        __syncthreads();
        for (int j = tid; j < KC; j += NTHREADS) {
            float s = 0.f;
#pragma unroll
            for (int k = 0; k < 8; k++) s += c2p[j * 8 + k];
            cw[j] = make_float2(l2nb * s, ews[j] * rden);
        }
        __syncthreads();   // scratch (A0/A1, f2p0) free after this
    }

    // ---- per-warp ldmatrix lane addressing ----
    const int rb  = (wid & 3) * 32;          // 32-row block
    const int cb0 = (wid >> 2) * 256;        // 256-col half
    const int ncrot = (wid & 1) * 4;         // anti-phase over 8 chunks
    const int arow = lane & 15;
    const uint32_t alx = (uint32_t)(((lane >> 4) * 16) ^ ((arow & 7) * 16));
    const uint32_t arowoff = (uint32_t)(rb + arow) * 128;
    const int bg = lane >> 3, br = lane & 7;
    const uint32_t blx = (uint32_t)(((bg & 1) * 16) ^ (br * 16));
    const int bnoff = br + (bg >> 1) * 8;

    // ---- prologue: convert first tile into buffer 0 ----
    {
        const float4* src = (const float4*)(F + (size_t)blockIdx.x * TM * DD);
        float* f2pn = (float*)(smem + SMEM_F2P0);
#pragma unroll
        for (int k = 0; k < 4; k++) {
            int i = tid + k * NTHREADS;
            int r = i >> 3, ck = i & 7;
            float v[8];
            *(float4*)&v[0] = src[2*i];
            *(float4*)&v[4] = src[2*i+1];
            uint4 hi; float ss = 0.f;
            round8(v, hi, ss);
            f2pn[i] = ss;
            uint32_t sw = SWZ128((uint32_t)(r * 128 + ck * 16));
            *(uint4*)(smem + SMEM_A0 + sw) = hi;
        }
    }

    int pcur = 0;

    // ================= tile loop (persistent) =================
#pragma unroll 1
    for (int t = blockIdx.x; t < NTILES; t += GRID, pcur ^= 1) {
        __syncthreads();   // B1: A(cur)/f2p(cur) conversion visible

        float* f2pc = (float*)(smem + (pcur ? SMEM_F2P1 : SMEM_F2P0));
        float* f2sc = (float*)(smem + (pcur ? SMEM_F2S1 : SMEM_F2S0));
        const uint32_t abase = sb + (pcur ? SMEM_A1 : SMEM_A0) + arowoff;

        if (tid < TM) {
            float s = 0.f;
#pragma unroll
            for (int k = 0; k < 8; k++) s += f2pc[tid * 8 + k];
            f2sc[tid] = l2nb * s;
        }
        __syncthreads();   // B2: f2s visible

        // cache A-hi fragments for all 4 k-steps (32 regs)
        uint32_t ahc[2][4][4];
#pragma unroll
        for (int kt = 0; kt < 4; kt++) {
            const uint32_t ka = ((uint32_t)(kt * 32)) ^ alx;
            ldsm4(abase + ka,        ahc[0][kt]);
            ldsm4(abase + 2048 + ka, ahc[1][kt]);
        }

        float score = 0.f;
        float accA[2][4][4], accB[2][4][4];

        // chunk 0 MMA
        {
            const int cb = cb0 + (ncrot & 7) * 32;
            mma_chunk32(accA, ahc, blx,
                        sb + SMEM_BH + (uint32_t)(cb + bnoff) * 128);
        }

        // prefetch+convert next tile (overlaps tensor work)
        if (t + GRID < NTILES) {
            const float4* src = (const float4*)(F + (size_t)(t + GRID) * TM * DD);
            float* f2pn = (float*)(smem + (pcur ? SMEM_F2P0 : SMEM_F2P1));
            const uint32_t an = (pcur ? SMEM_A0 : SMEM_A1);
#pragma unroll
            for (int k = 0; k < 4; k++) {
                int i = tid + k * NTHREADS;
                int r = i >> 3, ck = i & 7;
                float v[8];
                *(float4*)&v[0] = src[2*i];
                *(float4*)&v[4] = src[2*i+1];
                uint4 hi; float ss = 0.f;
                round8(v, hi, ss);
                f2pn[i] = ss;
                uint32_t sw = SWZ128((uint32_t)(r * 128 + ck * 16));
                *(uint4*)(smem + an + sw) = hi;
            }
        }

        // pipelined chunks 1..7: MMA(c) then epilogue(c-1)
#pragma unroll
        for (int c = 1; c < 8; c++) {
            const int cb  = cb0 + ((c + ncrot) & 7) * 32;
            const int cbp = cb0 + ((c - 1 + ncrot) & 7) * 32;
            if (c & 1) {
                mma_chunk32(accB, ahc, blx,
                            sb + SMEM_BH + (uint32_t)(cb + bnoff) * 128);
                epi_chunk32(accA, f2sc, cw, cbp, rb, lane, coef, score);
            } else {
                mma_chunk32(accA, ahc, blx,
                            sb + SMEM_BH + (uint32_t)(cb + bnoff) * 128);
                epi_chunk32(accB, f2sc, cw, cbp, rb, lane, coef, score);
            }
        }
        epi_chunk32(accB, f2sc, cw, cb0 + ((7 + ncrot) & 7) * 32, rb, lane, coef, score);

        // ---- shuffle reduction ----
#pragma unroll
        for (int o = 16; o > 0; o >>= 1)
            score += __shfl_xor_sync(0xFFFFFFFFu, score, o);
        if (lane == 0) red[wid] = score;
        __syncthreads();   // B3: red ready; all reads of cur buffers done
        if (tid == 0) {
            float s = 0.f;
#pragma unroll
            for (int w = 0; w < 8; w++) s += red[w];
            g_part[t] = s;
        }
    }

    // ---- last CTA folds partials into out ----
    __threadfence();
    if (tid == 0) {
        int p = atomicAdd(&g_count, 1);
        *flg = (p == GRID - 1);
    }
    __syncthreads();
    if (*flg) {
        __threadfence();
        if (tid < BB) {
            float s = 0.f;
#pragma unroll
            for (int i = 0; i < NTILES / BB; i++) s += g_part[tid * (NTILES / BB) + i];
            out[tid] = s * (1.0f / NN);
        }
        if (tid == 0) g_count = 0;   // reset for next graph replay
    }
}

// ---------------------------------------------------------------------------
extern "C" void kernel_launch(void* const* d_in, const int* in_sizes, int n_in,
                              void* d_out, int out_size) {
    const float* F       = (const float*)d_in[0];
    const float* centers = (const float*)d_in[1];
    const float* psi     = (const float*)d_in[2];
    const float* beta    = (const float*)d_in[3];
    float* out           = (float*)d_out;

    cudaFuncSetAttribute(main_kernel, cudaFuncAttributeMaxDynamicSharedMemorySize, SMEM_TOTAL);
    main_kernel<<<GRID, NTHREADS, SMEM_TOTAL>>>(F, centers, psi, beta, out);
}